// round 16
// baseline (speedup 1.0000x reference)
#include <cuda_runtime.h>
#include <cuda_fp16.h>
#include <math_constants.h>
#include <cstdint>

#define DIMC 1024
#define NB   8
#define SQL  2048
#define SKL  2048

// Static device scratch (allocation-free requirement)
__device__ __half g_Q [(long long)NB * SQL * DIMC];   // 32 MB fp16 Q
__device__ __half g_K [(long long)NB * SKL * DIMC];   // 32 MB fp16 K
__device__ __half g_Vt[(long long)NB * DIMC * SKL];   // 32 MB fp16 V^T [b][d][t]
__device__ float  g_S [(long long)NB * SQL * SKL];    // 128 MB fp32 scores
__device__ __half g_P [(long long)NB * SQL * SKL];    // 64 MB fp16 probs
__device__ __half g_Xh[(long long)NB * SQL * DIMC];   // 32 MB fp16 x
__device__ __half g_Ch[(long long)NB * SKL * DIMC];   // 32 MB fp16 ctx
__device__ __half g_Wh[3LL * DIMC * DIMC];            // 6 MB fp16 Wq,Wk,Wv

// ---------------------------------------------------------------------------
// helpers
// ---------------------------------------------------------------------------
__device__ __forceinline__ uint32_t smem_u32(const void* p) {
    uint32_t a;
    asm("{ .reg .u64 t; cvta.to.shared.u64 t, %1; cvt.u32.u64 %0, t; }" : "=r"(a) : "l"(p));
    return a;
}
__device__ __forceinline__ void mma_f16(float d[4], const uint32_t a[4], const uint32_t b[2]) {
    asm volatile(
        "mma.sync.aligned.m16n8k16.row.col.f32.f16.f16.f32 "
        "{%0,%1,%2,%3}, {%4,%5,%6,%7}, {%8,%9}, {%0,%1,%2,%3};"
        : "+f"(d[0]), "+f"(d[1]), "+f"(d[2]), "+f"(d[3])
        : "r"(a[0]), "r"(a[1]), "r"(a[2]), "r"(a[3]), "r"(b[0]), "r"(b[1]));
}
#define LDMX4(r0, r1, r2, r3, a) \
    asm volatile("ldmatrix.sync.aligned.m8n8.x4.shared.b16 {%0,%1,%2,%3}, [%4];" \
        : "=r"(r0), "=r"(r1), "=r"(r2), "=r"(r3) : "r"(a))
#define CP_ASYNC16(dst, src) \
    asm volatile("cp.async.cg.shared.global [%0], [%1], 16;" :: "r"(dst), "l"(src) : "memory")
#define CP_COMMIT() asm volatile("cp.async.commit_group;" ::: "memory")
#define CP_WAIT1()  asm volatile("cp.async.wait_group 1;" ::: "memory")

// Tile: 128(M) x 128(N) x 64(K); 128 threads = 4 warps (2m x 2n), warp 64x64.
// SMEM: 3 stages; stage = A 128x64 fp16 (16 KB) + B 128x64 fp16 (16 KB).
// 128 B per row, SW128 XOR swizzle (conflict-free cp.async + ldmatrix).
#define A_BYTES   (128 * 128)                // 16384
#define STAGE_B   (2 * A_BYTES)              // 32768
#define SMEM_SZ   (3 * STAGE_B)              // 98304

// ---------------------------------------------------------------------------
// fp16 mma.sync GEMM: C[128x128 tile] = scale * A[M,K] @ B[N,K]^T (+ bias)
// A, B fp16 K-major. MODE 0: fp32 out *scale. MODE 1: fp16 out (+bias).
// MODE 2: fp16 +bias, scatter into g_Vt [b][n][t] (t = global m row).
// Batched via blockIdx.z strides (element units).
// ---------------------------------------------------------------------------
__device__ __forceinline__ void load_stage_h(
    const __half* __restrict__ A, const __half* __restrict__ B,
    int K, long long k0, int bm, int bn, uint32_t as, uint32_t bs, int tid)
{
#pragma unroll
    for (int i = 0; i < 8; i++) {               // A: 128 rows x 8 chunks = 1024
        const int idx = tid + i * 128;
        const int row = idx >> 3;
        const int ch  = idx & 7;
        const uint32_t off = row * 128 + ((ch ^ (row & 7)) << 4);
        CP_ASYNC16(as + off, A + (long long)(bm + row) * K + k0 + ch * 8);
        CP_ASYNC16(bs + off, B + (long long)(bn + row) * K + k0 + ch * 8);
    }
}

template <int MODE>
__global__ void __launch_bounds__(128, 2)
mm_h(const __half* __restrict__ Ag, const __half* __restrict__ Bg,
     const float* __restrict__ bias, void* __restrict__ Cg,
     int K, int ldc, float scale,
     long long sA, long long sB, long long sC)
{
    extern __shared__ __align__(128) char smh[];
    const int tid  = threadIdx.x;
    const int wid  = tid >> 5;
    const int lane = tid & 31;
    const int wm = wid & 1;        // 2 x 64-row slabs
    const int wn = wid >> 1;       // 2 x 64-col slabs
    const int lr = lane >> 2;      // 0..7
    const int lc = lane & 3;       // 0..3

    const __half* A = Ag + (long long)blockIdx.z * sA;
    const __half* B = Bg + (long long)blockIdx.z * sB;
    const int bm = blockIdx.y * 128;
    const int bn = blockIdx.x * 128;

    const uint32_t sbase = smem_u32(smh);
    const int nk = K >> 6;

    // per-lane ldmatrix address components (R7-proven pattern)
    const int miA  = lane >> 3;           // 0..3: (m-half, k-half)
    const int rrA  = lane & 7;
    const int rowA = wm * 64 + (miA & 1) * 8 + rrA;
    const int khA  = miA >> 1;
    const int pB   = (lane >> 4) & 1;     // j within pair
    const int khB  = (lane >> 3) & 1;
    const int rrB  = lane & 7;

    float acc[4][8][4];
#pragma unroll
    for (int i = 0; i < 4; i++)
#pragma unroll
        for (int j = 0; j < 8; j++)
#pragma unroll
            for (int r = 0; r < 4; r++) acc[i][j][r] = 0.0f;

    // prologue: stages 0 and 1 in flight
    load_stage_h(A, B, K, 0, bm, bn, sbase, sbase + A_BYTES, tid);
    CP_COMMIT();
    if (nk > 1)
        load_stage_h(A, B, K, 64, bm, bn, sbase + STAGE_B, sbase + STAGE_B + A_BYTES, tid);
    CP_COMMIT();

    uint32_t a[2][4][4], bf[2][4][4];   // double-buffered fragments

    for (int kt = 0; kt < nk; kt++) {
        CP_WAIT1();          // stage kt done for this thread
        __syncthreads();     // ...for all threads; buffer (kt+2)%3 free

        if (kt + 2 < nk) {
            const uint32_t as = sbase + ((kt + 2) % 3) * STAGE_B;
            load_stage_h(A, B, K, (long long)(kt + 2) * 64, bm, bn, as, as + A_BYTES, tid);
        }
        CP_COMMIT();

        const uint32_t As = sbase + (kt % 3) * STAGE_B;
        const uint32_t Bs = As + A_BYTES;

        // fragment prefetch for ks=0
#pragma unroll
        for (int i = 0; i < 4; i++) {
            const uint32_t ad = As + (uint32_t)(rowA + i * 16) * 128
                              + (uint32_t)((khA ^ rrA) << 4);
            LDMX4(a[0][i][0], a[0][i][1], a[0][i][2], a[0][i][3], ad);
        }
#pragma unroll
        for (int jp = 0; jp < 4; jp++) {
            const int rowB = wn * 64 + jp * 16 + pB * 8 + rrB;
            const uint32_t bd = Bs + (uint32_t)rowB * 128
                              + (uint32_t)((khB ^ rrB) << 4);
            LDMX4(bf[0][jp][0], bf[0][jp][1], bf[0][jp][2], bf[0][jp][3], bd);
        }

#pragma unroll
        for (int ks = 0; ks < 4; ks++) {
            const int cur = ks & 1;
            const int nxt = cur ^ 1;
            if (ks < 3) {   // prefetch fragments for ks+1 while doing MMAs
#pragma unroll
                for (int i = 0; i < 4; i++) {
                    const uint32_t ad = As + (uint32_t)(rowA + i * 16) * 128
                                      + (uint32_t)(((2 * (ks + 1) + khA) ^ rrA) << 4);
                    LDMX4(a[nxt][i][0], a[nxt][i][1], a[nxt][i][2], a[nxt][i][3], ad);
                }
#pragma unroll
                for (int jp = 0; jp < 4; jp++) {
                    const int rowB = wn * 64 + jp * 16 + pB * 8 + rrB;
                    const uint32_t bd = Bs + (uint32_t)rowB * 128
                                      + (uint32_t)(((2 * (ks + 1) + khB) ^ rrB) << 4);
                    LDMX4(bf[nxt][jp][0], bf[nxt][jp][1], bf[nxt][jp][2], bf[nxt][jp][3], bd);
                }
            }
#pragma unroll
            for (int i = 0; i < 4; i++)
#pragma unroll
                for (int j = 0; j < 8; j++)
                    mma_f16(acc[i][j], a[cur][i], &bf[cur][j >> 1][(j & 1) * 2]);
        }
    }

    // epilogue: warp covers rows [wm*64, +64), cols [wn*64, +64)
    const int r0 = bm + wm * 64 + lr;
    const int c0 = bn + wn * 64 + lc * 2;

#pragma unroll
    for (int i = 0; i < 4; i++) {
        const int m1 = r0 + i * 16;
        const int m2 = m1 + 8;
#pragma unroll
        for (int j = 0; j < 8; j++) {
            const int n = c0 + j * 8;
            if (MODE == 2) {
                __half* Vt = (__half*)Cg;
                const int b1 = m1 >> 11, t1 = m1 & 2047;
                const int b2 = m2 >> 11, t2 = m2 & 2047;
                const float bx = bias[n], by = bias[n + 1];
                Vt[((long long)b1 * DIMC + n)     * SKL + t1] = __float2half_rn(acc[i][j][0] + bx);
                Vt[((long long)b1 * DIMC + n + 1) * SKL + t1] = __float2half_rn(acc[i][j][1] + by);
                Vt[((long long)b2 * DIMC + n)     * SKL + t2] = __float2half_rn(acc[i][j][2] + bx);
                Vt[((long long)b2 * DIMC + n + 1) * SKL + t2] = __float2half_rn(acc[i][j][3] + by);
            } else if (MODE == 1) {
                __half* C = (__half*)Cg + (long long)blockIdx.z * sC;
                const float bx = bias[n], by = bias[n + 1];
                __half2 v0 = __floats2half2_rn(acc[i][j][0] + bx, acc[i][j][1] + by);
                __half2 v1 = __floats2half2_rn(acc[i][j][2] + bx, acc[i][j][3] + by);
                *reinterpret_cast<__half2*>(C + (long long)m1 * ldc + n) = v0;
                *reinterpret_cast<__half2*>(C + (long long)m2 * ldc + n) = v1;
            } else {
                float* C = (float*)Cg + (long long)blockIdx.z * sC;
                float2 v0 = make_float2(acc[i][j][0] * scale, acc[i][j][1] * scale);
                float2 v1 = make_float2(acc[i][j][2] * scale, acc[i][j][3] * scale);
                *reinterpret_cast<float2*>(C + (long long)m1 * ldc + n) = v0;
                *reinterpret_cast<float2*>(C + (long long)m2 * ldc + n) = v1;
            }
        }
    }
}

// ---------------------------------------------------------------------------
// Fused round-to-fp16 pre-pass: one launch covers x, ctx, Wq, Wk, Wv.
// Chunk = 8 floats. Segments: [0,NX8) x, [NX8,2*NX8) ctx, then 3x NW8 for W.
// ---------------------------------------------------------------------------
#define NX8 ((long long)NB * SQL * DIMC / 8)   // 2097152
#define NW8 ((long long)DIMC * DIMC / 8)       // 131072
#define NTOT8 (2 * NX8 + 3 * NW8)

__global__ void __launch_bounds__(256)
round_all(const float* __restrict__ x, const float* __restrict__ ctx,
          const float* __restrict__ Wq, const float* __restrict__ Wk,
          const float* __restrict__ Wv,
          __half* __restrict__ Xh, __half* __restrict__ Ch, __half* __restrict__ Wh)
{
    const long long i = (long long)blockIdx.x * blockDim.x + threadIdx.x;
    if (i >= NTOT8) return;
    const float* src;
    __half* dst;
    long long o;
    if (i < NX8)                { src = x;   dst = Xh;                       o = i; }
    else if (i < 2 * NX8)       { src = ctx; dst = Ch;                       o = i - NX8; }
    else if (i < 2 * NX8 + NW8) { src = Wq;  dst = Wh;                       o = i - 2 * NX8; }
    else if (i < 2 * NX8 + 2 * NW8) { src = Wk; dst = Wh + DIMC * DIMC;      o = i - 2 * NX8 - NW8; }
    else                        { src = Wv;  dst = Wh + 2LL * DIMC * DIMC;   o = i - 2 * NX8 - 2 * NW8; }

    const float4* p = reinterpret_cast<const float4*>(src + o * 8);
    const float4 x0 = p[0];
    const float4 x1 = p[1];
    __half2 h[4];
    h[0] = __floats2half2_rn(x0.x, x0.y);
    h[1] = __floats2half2_rn(x0.z, x0.w);
    h[2] = __floats2half2_rn(x1.x, x1.y);
    h[3] = __floats2half2_rn(x1.z, x1.w);
    *reinterpret_cast<uint4*>(dst + o * 8) = *reinterpret_cast<uint4*>(h);
}

// ---------------------------------------------------------------------------
// Rowwise softmax over 2048 fp32 scores; writes fp16 probs. float4 loads.
// ---------------------------------------------------------------------------
__global__ void __launch_bounds__(256)
softmax_kernel(const float* __restrict__ S, __half* __restrict__ P)
{
    const float4* row = reinterpret_cast<const float4*>(S + (long long)blockIdx.x * SKL);
    __half2* prow = reinterpret_cast<__half2*>(P + (long long)blockIdx.x * SKL);
    const int tid = threadIdx.x;
    const int w = tid >> 5, l = tid & 31;

    __shared__ float sred[8];

    float v[8];
    {
        const float4 u0 = row[tid * 2];
        const float4 u1 = row[tid * 2 + 1];
        v[0] = u0.x; v[1] = u0.y; v[2] = u0.z; v[3] = u0.w;
        v[4] = u1.x; v[5] = u1.y; v[6] = u1.z; v[7] = u1.w;
    }
    float m = v[0];
#pragma unroll
    for (int i = 1; i < 8; i++) m = fmaxf(m, v[i]);
#pragma unroll
    for (int o = 16; o > 0; o >>= 1)
        m = fmaxf(m, __shfl_xor_sync(0xFFFFFFFFu, m, o));
    if (l == 0) sred[w] = m;
    __syncthreads();
    if (tid == 0) {
        float t = sred[0];
#pragma unroll
        for (int i = 1; i < 8; i++) t = fmaxf(t, sred[i]);
        sred[0] = t;
    }
    __syncthreads();
    const float rowmax = sred[0];
    __syncthreads();

    float s = 0.0f;
#pragma unroll
    for (int i = 0; i < 8; i++) {
        v[i] = __expf(v[i] - rowmax);
        s += v[i];
    }
#pragma unroll
    for (int o = 16; o > 0; o >>= 1)
        s += __shfl_xor_sync(0xFFFFFFFFu, s, o);
    if (l == 0) sred[w] = s;
    __syncthreads();
    if (tid == 0) {
        float t = 0.0f;
#pragma unroll
        for (int i = 0; i < 8; i++) t += sred[i];
        sred[0] = t;
    }
    __syncthreads();
    const float inv = 1.0f / sred[0];

#pragma unroll
    for (int i = 0; i < 4; i++)
        prow[tid * 4 + i] = __floats2half2_rn(v[2 * i] * inv, v[2 * i + 1] * inv);
}

// ---------------------------------------------------------------------------
// Launch
// ---------------------------------------------------------------------------
extern "C" void kernel_launch(void* const* d_in, const int* in_sizes, int n_in,
                              void* d_out, int out_size)
{
    const float* x   = (const float*)d_in[0];
    const float* ctx = (const float*)d_in[1];
    const float* Wq  = (const float*)d_in[2];
    const float* bq  = (const float*)d_in[3];
    const float* Wk  = (const float*)d_in[4];
    const float* bk  = (const float*)d_in[5];
    const float* Wv  = (const float*)d_in[6];
    const float* bv  = (const float*)d_in[7];
    float* out = (float*)d_out;

    __half *Q, *Kp, *Vt, *P, *Xh, *Ch, *Wh;
    float *S;
    cudaGetSymbolAddress((void**)&Q,  g_Q);
    cudaGetSymbolAddress((void**)&Kp, g_K);
    cudaGetSymbolAddress((void**)&Vt, g_Vt);
    cudaGetSymbolAddress((void**)&S,  g_S);
    cudaGetSymbolAddress((void**)&P,  g_P);
    cudaGetSymbolAddress((void**)&Xh, g_Xh);
    cudaGetSymbolAddress((void**)&Ch, g_Ch);
    cudaGetSymbolAddress((void**)&Wh, g_Wh);

    cudaFuncSetAttribute(mm_h<0>, cudaFuncAttributeMaxDynamicSharedMemorySize, SMEM_SZ);
    cudaFuncSetAttribute(mm_h<1>, cudaFuncAttributeMaxDynamicSharedMemorySize, SMEM_SZ);
    cudaFuncSetAttribute(mm_h<2>, cudaFuncAttributeMaxDynamicSharedMemorySize, SMEM_SZ);

    const float scale = 0.03125f;  // 1/sqrt(1024)

    // 0) fused round-to-fp16 (x, ctx, Wq, Wk, Wv in one launch)
    round_all<<<(unsigned)((NTOT8 + 255) / 256), 256>>>(x, ctx, Wq, Wk, Wv, Xh, Ch, Wh);

    // 1-3) projections (NT): [16384,1024] @ W^T + b -> fp16
    dim3 gp(DIMC / 128, (NB * SQL) / 128, 1);
    mm_h<1><<<gp, 128, SMEM_SZ>>>(Xh, Wh,                     bq, Q,  DIMC, DIMC, 1.0f, 0, 0, 0);
    mm_h<1><<<gp, 128, SMEM_SZ>>>(Ch, Wh + DIMC * DIMC,       bk, Kp, DIMC, DIMC, 1.0f, 0, 0, 0);
    mm_h<2><<<gp, 128, SMEM_SZ>>>(Ch, Wh + 2LL * DIMC * DIMC, bv, Vt, DIMC, 0,    1.0f, 0, 0, 0);

    // 4) scores (NT, batched): S = Q @ K^T * scale -> fp32
    dim3 gs(SKL / 128, SQL / 128, NB);
    mm_h<0><<<gs, 128, SMEM_SZ>>>(Q, Kp, nullptr, S, DIMC, SKL, scale,
                                  (long long)SQL * DIMC,
                                  (long long)SKL * DIMC,
                                  (long long)SQL * SKL);

    // 5) softmax -> fp16 probs
    softmax_kernel<<<NB * SQL, 256>>>(S, P);

    // 6) out = P @ Vt^T (NT, batched) -> fp32
    dim3 ga(DIMC / 128, SQL / 128, NB);
    mm_h<0><<<ga, 128, SMEM_SZ>>>(P, Vt, nullptr, out, SKL, DIMC, 1.0f,
                                  (long long)SQL * SKL,
                                  (long long)DIMC * SKL,
                                  (long long)SQL * DIMC);
}

// round 17
// speedup vs baseline: 1.0010x; 1.0010x over previous
#include <cuda_runtime.h>
#include <cuda_fp16.h>
#include <math_constants.h>
#include <cstdint>

#define DIMC 1024
#define NB   8
#define SQL  2048
#define SKL  2048

// Static device scratch (allocation-free requirement)
__device__ __half g_Q [(long long)NB * SQL * DIMC];   // 32 MB fp16 Q
__device__ __half g_K [(long long)NB * SKL * DIMC];   // 32 MB fp16 K
__device__ __half g_Vt[(long long)NB * DIMC * SKL];   // 32 MB fp16 V^T [b][d][t]
__device__ float  g_S [(long long)NB * SQL * SKL];    // 128 MB fp32 scores
__device__ __half g_P [(long long)NB * SQL * SKL];    // 64 MB fp16 probs
__device__ __half g_Xh[(long long)NB * SQL * DIMC];   // 32 MB fp16 x
__device__ __half g_Ch[(long long)NB * SKL * DIMC];   // 32 MB fp16 ctx
__device__ __half g_Wh[3LL * DIMC * DIMC];            // 6 MB fp16 Wq,Wk,Wv

// ---------------------------------------------------------------------------
// helpers
// ---------------------------------------------------------------------------
__device__ __forceinline__ uint32_t smem_u32(const void* p) {
    uint32_t a;
    asm("{ .reg .u64 t; cvta.to.shared.u64 t, %1; cvt.u32.u64 %0, t; }" : "=r"(a) : "l"(p));
    return a;
}
__device__ __forceinline__ void mma_f16(float d[4], const uint32_t a[4], const uint32_t b[2]) {
    asm volatile(
        "mma.sync.aligned.m16n8k16.row.col.f32.f16.f16.f32 "
        "{%0,%1,%2,%3}, {%4,%5,%6,%7}, {%8,%9}, {%0,%1,%2,%3};"
        : "+f"(d[0]), "+f"(d[1]), "+f"(d[2]), "+f"(d[3])
        : "r"(a[0]), "r"(a[1]), "r"(a[2]), "r"(a[3]), "r"(b[0]), "r"(b[1]));
}
#define LDMX4(r0, r1, r2, r3, a) \
    asm volatile("ldmatrix.sync.aligned.m8n8.x4.shared.b16 {%0,%1,%2,%3}, [%4];" \
        : "=r"(r0), "=r"(r1), "=r"(r2), "=r"(r3) : "r"(a))
#define CP_ASYNC16(dst, src) \
    asm volatile("cp.async.cg.shared.global [%0], [%1], 16;" :: "r"(dst), "l"(src) : "memory")
#define CP_COMMIT() asm volatile("cp.async.commit_group;" ::: "memory")
#define CP_WAIT1()  asm volatile("cp.async.wait_group 1;" ::: "memory")

// Tile: 128(M) x 128(N) x 64(K); 128 threads = 4 warps (2m x 2n), warp 64x64.
// SMEM: 3 stages; stage = A 128x64 fp16 (16 KB) + B 128x64 fp16 (16 KB).
// 128 B per row, SW128 XOR swizzle (conflict-free cp.async + ldmatrix).
#define A_BYTES   (128 * 128)                // 16384
#define STAGE_B   (2 * A_BYTES)              // 32768
#define SMEM_SZ   (3 * STAGE_B)              // 98304

// ---------------------------------------------------------------------------
// fp16 mma.sync GEMM: C[128x128 tile] = scale * A[M,K] @ B[N,K]^T (+ bias)
// A, B fp16 K-major. MODE 0: fp32 out *scale. MODE 1: fp16 out (+bias).
// MODE 2: fp16 +bias, scatter into g_Vt [b][n][t] (t = global m row).
// Batched via blockIdx.z strides (element units).
// ---------------------------------------------------------------------------
__device__ __forceinline__ void load_stage_h(
    const __half* __restrict__ A, const __half* __restrict__ B,
    int K, long long k0, int bm, int bn, uint32_t as, uint32_t bs, int tid)
{
#pragma unroll
    for (int i = 0; i < 8; i++) {               // A: 128 rows x 8 chunks = 1024
        const int idx = tid + i * 128;
        const int row = idx >> 3;
        const int ch  = idx & 7;
        const uint32_t off = row * 128 + ((ch ^ (row & 7)) << 4);
        CP_ASYNC16(as + off, A + (long long)(bm + row) * K + k0 + ch * 8);
        CP_ASYNC16(bs + off, B + (long long)(bn + row) * K + k0 + ch * 8);
    }
}

template <int MODE>
__global__ void __launch_bounds__(128, 2)
mm_h(const __half* __restrict__ Ag, const __half* __restrict__ Bg,
     const float* __restrict__ bias, void* __restrict__ Cg,
     int K, int ldc, float scale,
     long long sA, long long sB, long long sC)
{
    extern __shared__ __align__(128) char smh[];
    const int tid  = threadIdx.x;
    const int wid  = tid >> 5;
    const int lane = tid & 31;
    const int wm = wid & 1;        // 2 x 64-row slabs
    const int wn = wid >> 1;       // 2 x 64-col slabs
    const int lr = lane >> 2;      // 0..7
    const int lc = lane & 3;       // 0..3

    const __half* A = Ag + (long long)blockIdx.z * sA;
    const __half* B = Bg + (long long)blockIdx.z * sB;
    const int bm = blockIdx.y * 128;
    const int bn = blockIdx.x * 128;

    const uint32_t sbase = smem_u32(smh);
    const int nk = K >> 6;

    // per-lane ldmatrix address components (R7-proven pattern)
    const int miA  = lane >> 3;           // 0..3: (m-half, k-half)
    const int rrA  = lane & 7;
    const int rowA = wm * 64 + (miA & 1) * 8 + rrA;
    const int khA  = miA >> 1;
    const int pB   = (lane >> 4) & 1;     // j within pair
    const int khB  = (lane >> 3) & 1;
    const int rrB  = lane & 7;

    float acc[4][8][4];
#pragma unroll
    for (int i = 0; i < 4; i++)
#pragma unroll
        for (int j = 0; j < 8; j++)
#pragma unroll
            for (int r = 0; r < 4; r++) acc[i][j][r] = 0.0f;

    // prologue: stages 0 and 1 in flight
    load_stage_h(A, B, K, 0, bm, bn, sbase, sbase + A_BYTES, tid);
    CP_COMMIT();
    if (nk > 1)
        load_stage_h(A, B, K, 64, bm, bn, sbase + STAGE_B, sbase + STAGE_B + A_BYTES, tid);
    CP_COMMIT();

    uint32_t a[2][4][4], bf[2][4][4];   // double-buffered fragments

    for (int kt = 0; kt < nk; kt++) {
        CP_WAIT1();          // stage kt done for this thread
        __syncthreads();     // ...for all threads; buffer (kt+2)%3 free

        if (kt + 2 < nk) {
            const uint32_t as = sbase + ((kt + 2) % 3) * STAGE_B;
            load_stage_h(A, B, K, (long long)(kt + 2) * 64, bm, bn, as, as + A_BYTES, tid);
        }
        CP_COMMIT();

        const uint32_t As = sbase + (kt % 3) * STAGE_B;
        const uint32_t Bs = As + A_BYTES;

        // fragment prefetch for ks=0
#pragma unroll
        for (int i = 0; i < 4; i++) {
            const uint32_t ad = As + (uint32_t)(rowA + i * 16) * 128
                              + (uint32_t)((khA ^ rrA) << 4);
            LDMX4(a[0][i][0], a[0][i][1], a[0][i][2], a[0][i][3], ad);
        }
#pragma unroll
        for (int jp = 0; jp < 4; jp++) {
            const int rowB = wn * 64 + jp * 16 + pB * 8 + rrB;
            const uint32_t bd = Bs + (uint32_t)rowB * 128
                              + (uint32_t)((khB ^ rrB) << 4);
            LDMX4(bf[0][jp][0], bf[0][jp][1], bf[0][jp][2], bf[0][jp][3], bd);
        }

#pragma unroll
        for (int ks = 0; ks < 4; ks++) {
            const int cur = ks & 1;
            const int nxt = cur ^ 1;
            if (ks < 3) {   // prefetch fragments for ks+1 while doing MMAs
#pragma unroll
                for (int i = 0; i < 4; i++) {
                    const uint32_t ad = As + (uint32_t)(rowA + i * 16) * 128
                                      + (uint32_t)(((2 * (ks + 1) + khA) ^ rrA) << 4);
                    LDMX4(a[nxt][i][0], a[nxt][i][1], a[nxt][i][2], a[nxt][i][3], ad);
                }
#pragma unroll
                for (int jp = 0; jp < 4; jp++) {
                    const int rowB = wn * 64 + jp * 16 + pB * 8 + rrB;
                    const uint32_t bd = Bs + (uint32_t)rowB * 128
                                      + (uint32_t)(((2 * (ks + 1) + khB) ^ rrB) << 4);
                    LDMX4(bf[nxt][jp][0], bf[nxt][jp][1], bf[nxt][jp][2], bf[nxt][jp][3], bd);
                }
            }
#pragma unroll
            for (int i = 0; i < 4; i++)
#pragma unroll
                for (int j = 0; j < 8; j++)
                    mma_f16(acc[i][j], a[cur][i], &bf[cur][j >> 1][(j & 1) * 2]);
        }
    }

    // epilogue: warp covers rows [wm*64, +64), cols [wn*64, +64)
    const int r0 = bm + wm * 64 + lr;
    const int c0 = bn + wn * 64 + lc * 2;

#pragma unroll
    for (int i = 0; i < 4; i++) {
        const int m1 = r0 + i * 16;
        const int m2 = m1 + 8;
#pragma unroll
        for (int j = 0; j < 8; j++) {
            const int n = c0 + j * 8;
            if (MODE == 2) {
                __half* Vt = (__half*)Cg;
                const int b1 = m1 >> 11, t1 = m1 & 2047;
                const int b2 = m2 >> 11, t2 = m2 & 2047;
                const float bx = bias[n], by = bias[n + 1];
                Vt[((long long)b1 * DIMC + n)     * SKL + t1] = __float2half_rn(acc[i][j][0] + bx);
                Vt[((long long)b1 * DIMC + n + 1) * SKL + t1] = __float2half_rn(acc[i][j][1] + by);
                Vt[((long long)b2 * DIMC + n)     * SKL + t2] = __float2half_rn(acc[i][j][2] + bx);
                Vt[((long long)b2 * DIMC + n + 1) * SKL + t2] = __float2half_rn(acc[i][j][3] + by);
            } else if (MODE == 1) {
                __half* C = (__half*)Cg + (long long)blockIdx.z * sC;
                const float bx = bias[n], by = bias[n + 1];
                __half2 v0 = __floats2half2_rn(acc[i][j][0] + bx, acc[i][j][1] + by);
                __half2 v1 = __floats2half2_rn(acc[i][j][2] + bx, acc[i][j][3] + by);
                *reinterpret_cast<__half2*>(C + (long long)m1 * ldc + n) = v0;
                *reinterpret_cast<__half2*>(C + (long long)m2 * ldc + n) = v1;
            } else {
                float* C = (float*)Cg + (long long)blockIdx.z * sC;
                float2 v0 = make_float2(acc[i][j][0] * scale, acc[i][j][1] * scale);
                float2 v1 = make_float2(acc[i][j][2] * scale, acc[i][j][3] * scale);
                *reinterpret_cast<float2*>(C + (long long)m1 * ldc + n) = v0;
                *reinterpret_cast<float2*>(C + (long long)m2 * ldc + n) = v1;
            }
        }
    }
}

// ---------------------------------------------------------------------------
// Fused round-to-fp16 pre-pass: one launch covers x, ctx, Wq, Wk, Wv.
// Chunk = 8 floats. Segments: [0,NX8) x, [NX8,2*NX8) ctx, then 3x NW8 for W.
// ---------------------------------------------------------------------------
#define NX8 ((long long)NB * SQL * DIMC / 8)   // 2097152
#define NW8 ((long long)DIMC * DIMC / 8)       // 131072
#define NTOT8 (2 * NX8 + 3 * NW8)

__global__ void __launch_bounds__(256)
round_all(const float* __restrict__ x, const float* __restrict__ ctx,
          const float* __restrict__ Wq, const float* __restrict__ Wk,
          const float* __restrict__ Wv,
          __half* __restrict__ Xh, __half* __restrict__ Ch, __half* __restrict__ Wh)
{
    const long long i = (long long)blockIdx.x * blockDim.x + threadIdx.x;
    if (i >= NTOT8) return;
    const float* src;
    __half* dst;
    long long o;
    if (i < NX8)                { src = x;   dst = Xh;                       o = i; }
    else if (i < 2 * NX8)       { src = ctx; dst = Ch;                       o = i - NX8; }
    else if (i < 2 * NX8 + NW8) { src = Wq;  dst = Wh;                       o = i - 2 * NX8; }
    else if (i < 2 * NX8 + 2 * NW8) { src = Wk; dst = Wh + DIMC * DIMC;      o = i - 2 * NX8 - NW8; }
    else                        { src = Wv;  dst = Wh + 2LL * DIMC * DIMC;   o = i - 2 * NX8 - 2 * NW8; }

    const float4* p = reinterpret_cast<const float4*>(src + o * 8);
    const float4 x0 = p[0];
    const float4 x1 = p[1];
    __half2 h[4];
    h[0] = __floats2half2_rn(x0.x, x0.y);
    h[1] = __floats2half2_rn(x0.z, x0.w);
    h[2] = __floats2half2_rn(x1.x, x1.y);
    h[3] = __floats2half2_rn(x1.z, x1.w);
    *reinterpret_cast<uint4*>(dst + o * 8) = *reinterpret_cast<uint4*>(h);
}

// ---------------------------------------------------------------------------
// Rowwise softmax over 2048 fp32 scores; writes fp16 probs. float4 loads.
// ---------------------------------------------------------------------------
__global__ void __launch_bounds__(256)
softmax_kernel(const float* __restrict__ S, __half* __restrict__ P)
{
    const float4* row = reinterpret_cast<const float4*>(S + (long long)blockIdx.x * SKL);
    __half2* prow = reinterpret_cast<__half2*>(P + (long long)blockIdx.x * SKL);
    const int tid = threadIdx.x;
    const int w = tid >> 5, l = tid & 31;

    __shared__ float sred[8];

    float v[8];
    {
        const float4 u0 = row[tid * 2];
        const float4 u1 = row[tid * 2 + 1];
        v[0] = u0.x; v[1] = u0.y; v[2] = u0.z; v[3] = u0.w;
        v[4] = u1.x; v[5] = u1.y; v[6] = u1.z; v[7] = u1.w;
    }
    float m = v[0];
#pragma unroll
    for (int i = 1; i < 8; i++) m = fmaxf(m, v[i]);
#pragma unroll
    for (int o = 16; o > 0; o >>= 1)
        m = fmaxf(m, __shfl_xor_sync(0xFFFFFFFFu, m, o));
    if (l == 0) sred[w] = m;
    __syncthreads();
    if (tid == 0) {
        float t = sred[0];
#pragma unroll
        for (int i = 1; i < 8; i++) t = fmaxf(t, sred[i]);
        sred[0] = t;
    }
    __syncthreads();
    const float rowmax = sred[0];
    __syncthreads();

    float s = 0.0f;
#pragma unroll
    for (int i = 0; i < 8; i++) {
        v[i] = __expf(v[i] - rowmax);
        s += v[i];
    }
#pragma unroll
    for (int o = 16; o > 0; o >>= 1)
        s += __shfl_xor_sync(0xFFFFFFFFu, s, o);
    if (l == 0) sred[w] = s;
    __syncthreads();
    if (tid == 0) {
        float t = 0.0f;
#pragma unroll
        for (int i = 0; i < 8; i++) t += sred[i];
        sred[0] = t;
    }
    __syncthreads();
    const float inv = 1.0f / sred[0];

#pragma unroll
    for (int i = 0; i < 4; i++)
        prow[tid * 4 + i] = __floats2half2_rn(v[2 * i] * inv, v[2 * i + 1] * inv);
}

// ---------------------------------------------------------------------------
// Launch
// ---------------------------------------------------------------------------
extern "C" void kernel_launch(void* const* d_in, const int* in_sizes, int n_in,
                              void* d_out, int out_size)
{
    const float* x   = (const float*)d_in[0];
    const float* ctx = (const float*)d_in[1];
    const float* Wq  = (const float*)d_in[2];
    const float* bq  = (const float*)d_in[3];
    const float* Wk  = (const float*)d_in[4];
    const float* bk  = (const float*)d_in[5];
    const float* Wv  = (const float*)d_in[6];
    const float* bv  = (const float*)d_in[7];
    float* out = (float*)d_out;

    __half *Q, *Kp, *Vt, *P, *Xh, *Ch, *Wh;
    float *S;
    cudaGetSymbolAddress((void**)&Q,  g_Q);
    cudaGetSymbolAddress((void**)&Kp, g_K);
    cudaGetSymbolAddress((void**)&Vt, g_Vt);
    cudaGetSymbolAddress((void**)&S,  g_S);
    cudaGetSymbolAddress((void**)&P,  g_P);
    cudaGetSymbolAddress((void**)&Xh, g_Xh);
    cudaGetSymbolAddress((void**)&Ch, g_Ch);
    cudaGetSymbolAddress((void**)&Wh, g_Wh);

    cudaFuncSetAttribute(mm_h<0>, cudaFuncAttributeMaxDynamicSharedMemorySize, SMEM_SZ);
    cudaFuncSetAttribute(mm_h<1>, cudaFuncAttributeMaxDynamicSharedMemorySize, SMEM_SZ);
    cudaFuncSetAttribute(mm_h<2>, cudaFuncAttributeMaxDynamicSharedMemorySize, SMEM_SZ);

    const float scale = 0.03125f;  // 1/sqrt(1024)

    // 0) fused round-to-fp16 (x, ctx, Wq, Wk, Wv in one launch)
    round_all<<<(unsigned)((NTOT8 + 255) / 256), 256>>>(x, ctx, Wq, Wk, Wv, Xh, Ch, Wh);

    // 1-3) projections (NT): [16384,1024] @ W^T + b -> fp16
    dim3 gp(DIMC / 128, (NB * SQL) / 128, 1);
    mm_h<1><<<gp, 128, SMEM_SZ>>>(Xh, Wh,                     bq, Q,  DIMC, DIMC, 1.0f, 0, 0, 0);
    mm_h<1><<<gp, 128, SMEM_SZ>>>(Ch, Wh + DIMC * DIMC,       bk, Kp, DIMC, DIMC, 1.0f, 0, 0, 0);
    mm_h<2><<<gp, 128, SMEM_SZ>>>(Ch, Wh + 2LL * DIMC * DIMC, bv, Vt, DIMC, 0,    1.0f, 0, 0, 0);

    // 4) scores (NT, batched): S = Q @ K^T * scale -> fp32
    dim3 gs(SKL / 128, SQL / 128, NB);
    mm_h<0><<<gs, 128, SMEM_SZ>>>(Q, Kp, nullptr, S, DIMC, SKL, scale,
                                  (long long)SQL * DIMC,
                                  (long long)SKL * DIMC,
                                  (long long)SQL * SKL);

    // 5) softmax -> fp16 probs
    softmax_kernel<<<NB * SQL, 256>>>(S, P);

    // 6) out = P @ Vt^T (NT, batched) -> fp32
    dim3 ga(DIMC / 128, SQL / 128, NB);
    mm_h<0><<<ga, 128, SMEM_SZ>>>(P, Vt, nullptr, out, SKL, DIMC, 1.0f,
                                  (long long)SQL * SKL,
                                  (long long)DIMC * SKL,
                                  (long long)SQL * DIMC);
}